// round 6
// baseline (speedup 1.0000x reference)
#include <cuda_runtime.h>
#include <cuda_pipeline.h>
#include <cstdint>
#include <cstddef>

// Stereo cost volume:
//   out[bh, w, d] = sum_c ref[bh, w + 63 - d, c] * aux[bh, w, c]
// ref: [1536, 447, 128] f32, aux: [1536, 384, 128] f32, out: [1536, 384, 64] f32

namespace {

constexpr int kBH = 8 * 192;   // 1536
constexpr int kW  = 384;
constexpr int kC  = 128;
constexpr int kD  = 64;
constexpr int kRW = 447;       // ref width (384 + 63)

constexpr int WTILE  = 128;            // output w per CTA
constexpr int NREF   = WTILE + 63;     // 191 ref pixels per CTA
constexpr int NCP    = 8;              // channel-pairs per K chunk (16 channels)
constexpr int NCHUNK = (kC / 2) / NCP; // 8 chunks
constexpr int NTHREADS = 128;          // 16 w-tiles x 8 d-tiles, 8x8 micro-tile each

// SMEM layout in float2 (carried as unsigned long long):
//   plane-major [plane][pixel] with plane = cp ^ (pixel_block & 7).
//   Pitches are ≡2 (mod 16) words, which together with the plane XOR makes all
//   compute-side LDS.128 phases and staging STS.64 groups bank-conflict-free.
constexpr int RPITCH = 194;
constexpr int APITCH = 130;

__device__ __forceinline__ int ref_sidx(int cp, int r) {
    return (cp ^ ((r >> 3) & 7)) * RPITCH + r;
}
__device__ __forceinline__ int aux_sidx(int cp, int w) {
    return (cp ^ ((w >> 3) & 7)) * APITCH + w;
}

// Packed dual-fp32 FMA (Blackwell FFMA2): lanewise d = a*b + c on two f32.
__device__ __forceinline__ unsigned long long ffma2(unsigned long long a,
                                                    unsigned long long b,
                                                    unsigned long long c) {
    unsigned long long d;
    asm("fma.rn.f32x2 %0, %1, %2, %3;" : "=l"(d) : "l"(a), "l"(b), "l"(c));
    return d;
}

__device__ __forceinline__ float sum2(unsigned long long v) {
    float lo = __uint_as_float(static_cast<unsigned>(v & 0xffffffffull));
    float hi = __uint_as_float(static_cast<unsigned>(v >> 32));
    return lo + hi;
}

__global__ __launch_bounds__(NTHREADS, 2)
void cost_volume_kernel(const float* __restrict__ ref,
                        const float* __restrict__ aux,
                        float* __restrict__ out) {
    __shared__ unsigned long long sref[2][NCP * RPITCH];  // 2 x 12416 B
    __shared__ unsigned long long saux[2][NCP * APITCH];  // 2 x  8320 B

    const int tid   = threadIdx.x;
    const int bh    = blockIdx.y;
    const int wbase = blockIdx.x * WTILE;

    const float* refg = ref + ((size_t)bh * kRW + wbase) * kC;
    const float* auxg = aux + ((size_t)bh * kW  + wbase) * kC;

    // Stage one 16-channel chunk (as 8 channel-pairs) into buffer `buf`.
    auto stage = [&](int k, int buf) {
        const int coff = k * (2 * NCP);  // channel offset of this chunk
        // ref: 191 rows x 8 cpairs = 1528 8B copies
        #pragma unroll
        for (int it = 0; it < 12; ++it) {
            int id = tid + it * NTHREADS;
            if (id < NREF * NCP) {
                int cp = id & 7;
                int r  = id >> 3;
                const float* src = refg + (size_t)r * kC + coff + 2 * cp;
                __pipeline_memcpy_async(&sref[buf][ref_sidx(cp, r)], src, 8);
            }
        }
        // aux: 128 rows x 8 cpairs = 1024 8B copies
        #pragma unroll
        for (int it = 0; it < 8; ++it) {
            int id = tid + it * NTHREADS;
            int cp = id & 7;
            int w  = id >> 3;
            const float* src = auxg + (size_t)w * kC + coff + 2 * cp;
            __pipeline_memcpy_async(&saux[buf][aux_sidx(cp, w)], src, 8);
        }
        __pipeline_commit();
    };

    const int wt = tid & 15;   // w tile index (0..15)  -> w0 = 8*wt
    const int dt = tid >> 4;   // d tile index (0..7)   -> d0 = 8*dt
    const int w0 = wt * 8;
    const int r0 = (wt - dt) * 8 + 56;  // window base: r(i,dd) = r0 + (i + 7 - dd)

    // acc[i][dd] = f32x2 {sum over even channels, sum over odd channels}
    unsigned long long acc[8][8];
    #pragma unroll
    for (int i = 0; i < 8; ++i)
        #pragma unroll
        for (int j = 0; j < 8; ++j)
            acc[i][j] = 0ull;

    stage(0, 0);

    for (int k = 0; k < NCHUNK; ++k) {
        const int buf = k & 1;
        if (k + 1 < NCHUNK) {
            stage(k + 1, buf ^ 1);
            __pipeline_wait_prior(1);
        } else {
            __pipeline_wait_prior(0);
        }
        __syncthreads();

        #pragma unroll
        for (int cp = 0; cp < NCP; ++cp) {
            // aux window: 8 consecutive w (single 8-block -> single plane)
            const unsigned long long* A = &saux[buf][aux_sidx(cp, w0)];
            unsigned long long av[8];
            #pragma unroll
            for (int q = 0; q < 4; ++q) {
                ulonglong2 t = *reinterpret_cast<const ulonglong2*>(A + 2 * q);
                av[2 * q] = t.x; av[2 * q + 1] = t.y;
            }
            // ref window: 16 pixels, spans two 8-blocks (two swizzle planes)
            const unsigned long long* R0 = &sref[buf][ref_sidx(cp, r0)];
            const unsigned long long* R1 = &sref[buf][ref_sidx(cp, r0 + 8)];
            unsigned long long rw[16];
            #pragma unroll
            for (int q = 0; q < 4; ++q) {
                ulonglong2 t0 = *reinterpret_cast<const ulonglong2*>(R0 + 2 * q);
                rw[2 * q]     = t0.x; rw[2 * q + 1]     = t0.y;
                ulonglong2 t1 = *reinterpret_cast<const ulonglong2*>(R1 + 2 * q);
                rw[8 + 2 * q] = t1.x; rw[8 + 2 * q + 1] = t1.y;
            }
            // 8w x 8d micro-tile, packed dual-FMA (128 fp32 FMAs per cp step)
            #pragma unroll
            for (int i = 0; i < 8; ++i)
                #pragma unroll
                for (int dd = 0; dd < 8; ++dd)
                    acc[i][dd] = ffma2(av[i], rw[i + 7 - dd], acc[i][dd]);
        }
        __syncthreads();
    }

    // Epilogue: out[bh][wbase + w0 + i][8*dt + dd] = acc.lo + acc.hi
    float* op = out + ((size_t)bh * kW + wbase + w0) * kD + dt * 8;
    #pragma unroll
    for (int i = 0; i < 8; ++i) {
        float4 v0, v1;
        v0.x = sum2(acc[i][0]); v0.y = sum2(acc[i][1]);
        v0.z = sum2(acc[i][2]); v0.w = sum2(acc[i][3]);
        v1.x = sum2(acc[i][4]); v1.y = sum2(acc[i][5]);
        v1.z = sum2(acc[i][6]); v1.w = sum2(acc[i][7]);
        *reinterpret_cast<float4*>(op + (size_t)i * kD)     = v0;
        *reinterpret_cast<float4*>(op + (size_t)i * kD + 4) = v1;
    }
}

}  // namespace

extern "C" void kernel_launch(void* const* d_in, const int* in_sizes, int n_in,
                              void* d_out, int out_size) {
    const float* ref = (const float*)d_in[0];  // [1536, 447, 128] f32
    const float* aux = (const float*)d_in[1];  // [1536, 384, 128] f32
    float* out = (float*)d_out;                // [1536, 384, 64]  f32
    (void)in_sizes; (void)n_in; (void)out_size;

    dim3 grid(kW / WTILE, kBH);  // (3, 1536)
    cost_volume_kernel<<<grid, NTHREADS>>>(ref, aux, out);
}